// round 16
// baseline (speedup 1.0000x reference)
#include <cuda_runtime.h>
#include <cstdint>

// SignedAttention R11: R9 compute phases, but each CTA processes patches
// (p, p+1) SEQUENTIALLY with double-buffered Q+K cp.async prefetch: patch
// p+1's staging drains in the background while patch p computes.

constexpr int Lv   = 1024;
constexpr int Dv   = 64;
constexpr int NP   = 128;
constexpr int CH   = 8;
constexpr int MAXK = 72;
constexpr int KP   = 68;   // K pitch: quad stride 17 (odd, 17%8=1) -> CF rows
constexpr int AP   = 9;    // score pitch: gcd(9,32)=1 -> CF scalar access
constexpr int TP   = 76;   // at_t pitch: CF quad reads
constexpr int NT   = 256;
constexpr int NPAIR= NP / 2;

using u64 = unsigned long long;

struct __align__(16) Smem {
    float qs[2][CH][Dv];      // 4 KB   (double-buffered)
    float ks[2][MAXK][KP];    // 38.3 KB (double-buffered)
    float at2[2][MAXK][AP];   // 5.1 KB : raw score halves [h][key][q]
    float at_t[CH][TP];       // 2.4 KB : weights [q][key]
    float part[CH][Dv];       // 2 KB   : phase-3 partials
};                            // ~52.9 KB -> 4 CTAs/SM

__device__ __forceinline__ void cp16(void* dst, const void* src) {
    uint32_t d = (uint32_t)__cvta_generic_to_shared(dst);
    asm volatile("cp.async.cg.shared.global [%0], [%1], 16;" :: "r"(d), "l"(src));
}
__device__ __forceinline__ void cp_commit() { asm volatile("cp.async.commit_group;"); }
__device__ __forceinline__ void cp_wait1()  { asm volatile("cp.async.wait_group 1;"); }
__device__ __forceinline__ void cp_wait0()  { asm volatile("cp.async.wait_group 0;"); }

__device__ __forceinline__ u64 pack2(float lo, float hi) {
    u64 r; asm("mov.b64 %0, {%1, %2};" : "=l"(r) : "f"(lo), "f"(hi)); return r;
}
__device__ __forceinline__ void ffma2(u64& acc, u64 a, u64 b) {
    asm("fma.rn.f32x2 %0, %1, %2, %0;" : "+l"(acc) : "l"(a), "l"(b));
}
__device__ __forceinline__ float2 unpack2(u64 v) {
    float lo, hi; asm("mov.b64 {%0, %1}, %2;" : "=f"(lo), "=f"(hi) : "l"(v));
    return make_float2(lo, hi);
}

// Stage Q (8x64) + K (nk x 64) for one patch into buffer `buf`.
__device__ __forceinline__ void stage_qk(Smem& sm, int buf,
                                         const float* __restrict__ Q,
                                         const float* __restrict__ K,
                                         size_t qbase, size_t kbase,
                                         int nk, int tid)
{
    if (tid < (CH * Dv) / 4) {
        int r = tid >> 4, c = tid & 15;
        cp16(&sm.qs[buf][r][c * 4], (const float4*)(Q + qbase) + tid);
    }
    const float4* Kg = (const float4*)(K + kbase);
    const int n4 = nk * (Dv / 4);
    for (int idx = tid; idx < n4; idx += NT) {
        int r = idx >> 4, c = idx & 15;
        cp16(&sm.ks[buf][r][c * 4], Kg + idx);
    }
    cp_commit();
}

// R9 phases 1-3 on buffer `buf`. Caller guarantees data is visible (barrier).
__device__ __forceinline__ void compute_patch(Smem& sm, int buf,
                                              const float* __restrict__ V,
                                              float* __restrict__ O,
                                              size_t qbase, size_t kbase,
                                              int nk, float scale,
                                              int warp, int lane)
{
    // ---- phase 1: 6 warps = (3 key-groups) x (2 d-halves); FFMA2, 8 q accs ----
    if (warp < 6) {
        const int h = (warp >= 3) ? 1 : 0;
        const int j = (warp - 3 * h) * 32 + lane;
        if (j < nk) {
            const int db = h * 8;
            u64 acc[CH] = {0,0,0,0,0,0,0,0};
            #pragma unroll
            for (int dd = 0; dd < 8; dd++) {
                const int c = (db + dd) * 4;
                const float4 kf = *(const float4*)&sm.ks[buf][j][c];
                const u64 k01 = pack2(kf.x, kf.y);
                const u64 k23 = pack2(kf.z, kf.w);
                #pragma unroll
                for (int qi = 0; qi < CH; qi++) {
                    const float4 qf = *(const float4*)&sm.qs[buf][qi][c];
                    ffma2(acc[qi], pack2(qf.x, qf.y), k01);
                    ffma2(acc[qi], pack2(qf.z, qf.w), k23);
                }
            }
            #pragma unroll
            for (int qi = 0; qi < CH; qi++) {
                const float2 s = unpack2(acc[qi]);
                sm.at2[h][j][qi] = s.x + s.y;        // pitch-9: CF
            }
        }
    }
    __syncthreads();

    // ---- phase 2: warp q -> dual softmax (adds d-halves); write transposed ----
    {
        const int q = warp;
        const bool v0 = (lane      < nk);
        const bool v1 = (lane + 32 < nk);
        const bool v2 = (lane + 64 < nk);
        const float t0 = v0 ? (sm.at2[0][lane     ][q] + sm.at2[1][lane     ][q]) * scale : 0.0f;
        const float t1 = v1 ? (sm.at2[0][lane + 32][q] + sm.at2[1][lane + 32][q]) * scale : 0.0f;
        const float t2 = v2 ? (sm.at2[0][lane + 64][q] + sm.at2[1][lane + 64][q]) * scale : 0.0f;

        float mx = -1e30f, mn = 1e30f;
        if (v0) { mx = fmaxf(mx, t0); mn = fminf(mn, t0); }
        if (v1) { mx = fmaxf(mx, t1); mn = fminf(mn, t1); }
        if (v2) { mx = fmaxf(mx, t2); mn = fminf(mn, t2); }
        #pragma unroll
        for (int o = 16; o; o >>= 1) {
            mx = fmaxf(mx, __shfl_xor_sync(0xffffffffu, mx, o));
            mn = fminf(mn, __shfl_xor_sync(0xffffffffu, mn, o));
        }

        float sp = 0.0f, sn = 0.0f;
        float e0p=0, e0n=0, e1p=0, e1n=0, e2p=0, e2n=0;
        if (v0) { e0p = __expf(t0 - mx); e0n = __expf(mn - t0); sp += e0p; sn += e0n; }
        if (v1) { e1p = __expf(t1 - mx); e1n = __expf(mn - t1); sp += e1p; sn += e1n; }
        if (v2) { e2p = __expf(t2 - mx); e2n = __expf(mn - t2); sp += e2p; sn += e2n; }
        #pragma unroll
        for (int o = 16; o; o >>= 1) {
            sp += __shfl_xor_sync(0xffffffffu, sp, o);
            sn += __shfl_xor_sync(0xffffffffu, sn, o);
        }
        const float rp = 1.0f / sp;
        const float rn = 1.0f / sn;
        if (v0) sm.at_t[q][lane     ] = e0p * rp - e0n * rn;
        if (v1) sm.at_t[q][lane + 32] = e1p * rp - e1n * rn;
        if (v2) sm.at_t[q][lane + 64] = e2p * rp - e2n * rn;
    }
    __syncthreads();

    // ---- phase 3: key-halves x 16-wide d-slices; V direct LDG, FFMA2 ----
    {
        const int w4   = warp & 3;
        const int q    = lane >> 2;
        const int dof  = w4 * 16 + (lane & 3) * 4;
        const int half = nk >> 1;
        const int j0   = (warp >= 4) ? half : 0;
        const int j1   = j0 + half;

        const float4* __restrict__ Vg =
            (const float4*)(V + kbase + dof) + (size_t)j0 * (Dv / 4);

        u64 a01 = 0, a23 = 0;
        #pragma unroll 4
        for (int j = j0; j < j1; j += 4) {
            const float4 a4 = *(const float4*)&sm.at_t[q][j];
            float4 vv; u64 aa;
            vv = Vg[0 * (Dv / 4)]; aa = pack2(a4.x, a4.x);
            ffma2(a01, pack2(vv.x, vv.y), aa);
            ffma2(a23, pack2(vv.z, vv.w), aa);
            vv = Vg[1 * (Dv / 4)]; aa = pack2(a4.y, a4.y);
            ffma2(a01, pack2(vv.x, vv.y), aa);
            ffma2(a23, pack2(vv.z, vv.w), aa);
            vv = Vg[2 * (Dv / 4)]; aa = pack2(a4.z, a4.z);
            ffma2(a01, pack2(vv.x, vv.y), aa);
            ffma2(a23, pack2(vv.z, vv.w), aa);
            vv = Vg[3 * (Dv / 4)]; aa = pack2(a4.w, a4.w);
            ffma2(a01, pack2(vv.x, vv.y), aa);
            ffma2(a23, pack2(vv.z, vv.w), aa);
            Vg += 4 * (Dv / 4);
        }
        const float2 e01 = unpack2(a01);
        const float2 e23 = unpack2(a23);
        float4 acc = make_float4(e01.x, e01.y, e23.x, e23.y);

        if (warp >= 4)
            *(float4*)&sm.part[q][dof] = acc;
        __syncthreads();
        if (warp < 4) {
            const float4 pp = *(const float4*)&sm.part[q][dof];
            acc.x += pp.x; acc.y += pp.y; acc.z += pp.z; acc.w += pp.w;
            *(float4*)(O + qbase + (size_t)q * Dv + dof) = acc;
        }
    }
}

__global__ __launch_bounds__(NT, 4)
void signed_attn_kernel(const float* __restrict__ Q,
                        const float* __restrict__ K,
                        const float* __restrict__ V,
                        const float* __restrict__ LS,
                        float* __restrict__ O)
{
    extern __shared__ unsigned char smem_raw[];
    Smem& sm = *reinterpret_cast<Smem*>(smem_raw);

    const int bh   = blockIdx.x / NPAIR;
    const int p0   = (blockIdx.x % NPAIR) * 2;          // even patch <= 126
    const int tid  = threadIdx.x;
    const int warp = tid >> 5;
    const int lane = tid & 31;

    const size_t qbase0 = ((size_t)bh * Lv + (size_t)p0 * CH) * Dv;
    const size_t kbase0 = qbase0 + CH * Dv;             // keys start at patch p0+1
    const size_t qbase1 = qbase0 + CH * Dv;
    const size_t kbase1 = kbase0 + CH * Dv;

    const int nk0 = min(9, NP - 1 - p0) * CH;           // >= 8 always (p0 <= 126)
    const int nk1 = min(9, NP - 2 - p0) * CH;           // 0 when p0 == 126

    // ---- stage patch 0, then (if valid) prefetch patch 1 ----
    stage_qk(sm, 0, Q, K, qbase0, kbase0, nk0, tid);
    const bool has2 = (nk1 > 0);
    if (has2) stage_qk(sm, 1, Q, K, qbase1, kbase1, nk1, tid);

    const float scale = fminf(fmaxf(expf(LS[0]), 1.0f), 30.0f) * 0.125f;

    if (has2) cp_wait1(); else cp_wait0();              // buf0 ready
    __syncthreads();

    compute_patch(sm, 0, V, O, qbase0, kbase0, nk0, scale, warp, lane);

    if (has2) {
        cp_wait0();                                     // buf1 ready (drained
        __syncthreads();                                //  during patch-0 compute)
        compute_patch(sm, 1, V, O, qbase1, kbase1, nk1, scale, warp, lane);
    } else {
        // patch 127: fully masked -> A == 0 exactly
        O[qbase1 + tid]      = 0.0f;
        O[qbase1 + tid + NT] = 0.0f;
    }
}

extern "C" void kernel_launch(void* const* d_in, const int* in_sizes, int n_in,
                              void* d_out, int out_size)
{
    const float* Q  = (const float*)d_in[0];
    const float* K  = (const float*)d_in[1];
    const float* V  = (const float*)d_in[2];
    const float* LS = (const float*)d_in[3];
    float* O = (float*)d_out;

    const int BH = in_sizes[0] / (Lv * Dv);   // B*H = 32
    const int smem_bytes = (int)sizeof(Smem);
    cudaFuncSetAttribute(signed_attn_kernel,
                         cudaFuncAttributeMaxDynamicSharedMemorySize, smem_bytes);
    signed_attn_kernel<<<BH * NPAIR, NT, smem_bytes>>>(Q, K, V, LS, O);
}

// round 17
// speedup vs baseline: 1.1265x; 1.1265x over previous
#include <cuda_runtime.h>
#include <cstdint>

// SignedAttention R12: R9 base + r=3 key-blocked phase 1 (Q broadcasts
// 384->128 wf) on 4 d-quarter warps with scalar f32 accumulators.

constexpr int Lv   = 1024;
constexpr int Dv   = 64;
constexpr int NP   = 128;
constexpr int CH   = 8;
constexpr int MAXK = 72;
constexpr int KP   = 76;   // K pitch: quad stride 19 -> CF row reads
constexpr int AP   = 9;    // score pitch: gcd(9,32)=1 -> CF scalar access
constexpr int TP   = 76;   // at_t pitch: CF quad reads
constexpr int NT   = 256;

using u64 = unsigned long long;

__device__ __forceinline__ void cp16(void* dst, const void* src) {
    uint32_t d = (uint32_t)__cvta_generic_to_shared(dst);
    asm volatile("cp.async.cg.shared.global [%0], [%1], 16;" :: "r"(d), "l"(src));
}
__device__ __forceinline__ void cp_commit() { asm volatile("cp.async.commit_group;"); }
__device__ __forceinline__ void cp_wait0()  { asm volatile("cp.async.wait_group 0;"); }

__device__ __forceinline__ u64 pack2(float lo, float hi) {
    u64 r; asm("mov.b64 %0, {%1, %2};" : "=l"(r) : "f"(lo), "f"(hi)); return r;
}
__device__ __forceinline__ void ffma2(u64& acc, u64 a, u64 b) {
    asm("fma.rn.f32x2 %0, %1, %2, %0;" : "+l"(acc) : "l"(a), "l"(b));
}
__device__ __forceinline__ float2 unpack2(u64 v) {
    float lo, hi; asm("mov.b64 {%0, %1}, %2;" : "=f"(lo), "=f"(hi) : "l"(v));
    return make_float2(lo, hi);
}

__global__ __launch_bounds__(NT, 5)
void signed_attn_kernel(const float* __restrict__ Q,
                        const float* __restrict__ K,
                        const float* __restrict__ V,
                        const float* __restrict__ LS,
                        float* __restrict__ O)
{
    __shared__ float qs[CH][Dv];           // 2 KB
    __shared__ float ks[MAXK][KP];         // 21.4 KB
    __shared__ float at4[4][MAXK][AP];     // 10.1 KB : d-quarter score partials
    __shared__ float at_t[CH][TP];         // 2.4 KB : weights [q][key]
    __shared__ float part[CH][Dv];         // 2 KB : phase-3 partials (~37.9 KB)

    const int bh   = blockIdx.x / NP;
    const int p    = blockIdx.x % NP;
    const int tid  = threadIdx.x;
    const int warp = tid >> 5;
    const int lane = tid & 31;

    const size_t qbase = ((size_t)bh * Lv + (size_t)p * CH) * Dv;

    const int npk = min(9, NP - 1 - p);
    const int nk  = npk * CH;              // multiple of 8, 0..72

    if (nk == 0) {                         // last patch: A == 0 exactly
        O[qbase + tid]      = 0.0f;
        O[qbase + tid + NT] = 0.0f;
        return;
    }

    // ---- stage Q + K via cp.async (V is NOT staged) ----
    const size_t kbase = ((size_t)bh * Lv + (size_t)(p + 1) * CH) * Dv;
    const int n4 = nk * (Dv / 4);
    {
        if (tid < (CH * Dv) / 4) {
            int r = tid >> 4, c = tid & 15;
            cp16(&qs[r][c * 4], (const float4*)(Q + qbase) + tid);
        }
        const float4* Kg = (const float4*)(K + kbase);
        for (int idx = tid; idx < n4; idx += NT) {
            int r = idx >> 4, c = idx & 15;
            cp16(&ks[r][c * 4], Kg + idx);
        }
        cp_commit();
    }

    const float scale = fminf(fmaxf(expf(LS[0]), 1.0f), 30.0f) * 0.125f;

    cp_wait0();
    __syncthreads();

    // ---- phase 1: 4 warps = d-quarters; lane covers keys {l, l+32, l+64} ----
    // Q broadcasts amortized over r=3 keys: 128 wf total instead of 384.
    if (warp < 4) {
        const int h  = warp;                      // d-quarter: quads [4h, 4h+4)
        const bool p0 = (lane      < nk);
        const bool p1 = (lane + 32 < nk);
        const bool p2 = (lane + 64 < nk);
        const int  j0 = lane;                     // may be >= nk (masked at store)
        const int  j1 = p1 ? lane + 32 : 0;       // clamp: garbage ok, never stored
        const int  j2 = p2 ? lane + 64 : 0;
        const int  j0c = p0 ? j0 : 0;

        float a0[CH] = {0,0,0,0,0,0,0,0};
        float a1[CH] = {0,0,0,0,0,0,0,0};
        float a2[CH] = {0,0,0,0,0,0,0,0};

        #pragma unroll
        for (int dd = 0; dd < 4; dd++) {
            const int c = (h * 4 + dd) * 4;
            const float4 k0 = *(const float4*)&ks[j0c][c];
            const float4 k1 = *(const float4*)&ks[j1][c];
            const float4 k2 = *(const float4*)&ks[j2][c];
            #pragma unroll
            for (int qi = 0; qi < CH; qi++) {
                const float4 qf = *(const float4*)&qs[qi][c];
                a0[qi] = fmaf(qf.x, k0.x, a0[qi]);
                a0[qi] = fmaf(qf.y, k0.y, a0[qi]);
                a0[qi] = fmaf(qf.z, k0.z, a0[qi]);
                a0[qi] = fmaf(qf.w, k0.w, a0[qi]);
                a1[qi] = fmaf(qf.x, k1.x, a1[qi]);
                a1[qi] = fmaf(qf.y, k1.y, a1[qi]);
                a1[qi] = fmaf(qf.z, k1.z, a1[qi]);
                a1[qi] = fmaf(qf.w, k1.w, a1[qi]);
                a2[qi] = fmaf(qf.x, k2.x, a2[qi]);
                a2[qi] = fmaf(qf.y, k2.y, a2[qi]);
                a2[qi] = fmaf(qf.z, k2.z, a2[qi]);
                a2[qi] = fmaf(qf.w, k2.w, a2[qi]);
            }
        }
        #pragma unroll
        for (int qi = 0; qi < CH; qi++) {
            if (p0) at4[h][j0][qi] = a0[qi];       // pitch-9: CF dense stores
            if (p1) at4[h][j1][qi] = a1[qi];
            if (p2) at4[h][j2][qi] = a2[qi];
        }
    }
    __syncthreads();

    // ---- phase 2: warp q -> dual softmax (merges 4 d-quarters) ----
    {
        const int q = warp;
        const bool v0 = (lane      < nk);
        const bool v1 = (lane + 32 < nk);
        const bool v2 = (lane + 64 < nk);
        const float t0 = v0 ? (at4[0][lane     ][q] + at4[1][lane     ][q]
                             + at4[2][lane     ][q] + at4[3][lane     ][q]) * scale : 0.0f;
        const float t1 = v1 ? (at4[0][lane + 32][q] + at4[1][lane + 32][q]
                             + at4[2][lane + 32][q] + at4[3][lane + 32][q]) * scale : 0.0f;
        const float t2 = v2 ? (at4[0][lane + 64][q] + at4[1][lane + 64][q]
                             + at4[2][lane + 64][q] + at4[3][lane + 64][q]) * scale : 0.0f;

        float mx = -1e30f, mn = 1e30f;
        if (v0) { mx = fmaxf(mx, t0); mn = fminf(mn, t0); }
        if (v1) { mx = fmaxf(mx, t1); mn = fminf(mn, t1); }
        if (v2) { mx = fmaxf(mx, t2); mn = fminf(mn, t2); }
        #pragma unroll
        for (int o = 16; o; o >>= 1) {
            mx = fmaxf(mx, __shfl_xor_sync(0xffffffffu, mx, o));
            mn = fminf(mn, __shfl_xor_sync(0xffffffffu, mn, o));
        }

        float sp = 0.0f, sn = 0.0f;
        float e0p=0, e0n=0, e1p=0, e1n=0, e2p=0, e2n=0;
        if (v0) { e0p = __expf(t0 - mx); e0n = __expf(mn - t0); sp += e0p; sn += e0n; }
        if (v1) { e1p = __expf(t1 - mx); e1n = __expf(mn - t1); sp += e1p; sn += e1n; }
        if (v2) { e2p = __expf(t2 - mx); e2n = __expf(mn - t2); sp += e2p; sn += e2n; }
        #pragma unroll
        for (int o = 16; o; o >>= 1) {
            sp += __shfl_xor_sync(0xffffffffu, sp, o);
            sn += __shfl_xor_sync(0xffffffffu, sn, o);
        }
        const float rp = 1.0f / sp;
        const float rn = 1.0f / sn;
        if (v0) at_t[q][lane     ] = e0p * rp - e0n * rn;
        if (v1) at_t[q][lane + 32] = e1p * rp - e1n * rn;
        if (v2) at_t[q][lane + 64] = e2p * rp - e2n * rn;
    }
    __syncthreads();

    // ---- phase 3: key-halves x 16-wide d-slices; V direct LDG, FFMA2 ----
    {
        const int w4   = warp & 3;
        const int q    = lane >> 2;                     // 0..7
        const int dof  = w4 * 16 + (lane & 3) * 4;      // float4 slice
        const int half = nk >> 1;                       // multiple of 4
        const int j0   = (warp >= 4) ? half : 0;
        const int j1   = j0 + half;

        const float4* __restrict__ Vg =
            (const float4*)(V + kbase + dof) + (size_t)j0 * (Dv / 4);

        u64 a01 = 0, a23 = 0;                           // packed d-pair accs
        #pragma unroll 4
        for (int j = j0; j < j1; j += 4) {
            const float4 a4 = *(const float4*)&at_t[q][j];   // CF quad read
            float4 vv; u64 aa;
            vv = Vg[0 * (Dv / 4)]; aa = pack2(a4.x, a4.x);
            ffma2(a01, pack2(vv.x, vv.y), aa);
            ffma2(a23, pack2(vv.z, vv.w), aa);
            vv = Vg[1 * (Dv / 4)]; aa = pack2(a4.y, a4.y);
            ffma2(a01, pack2(vv.x, vv.y), aa);
            ffma2(a23, pack2(vv.z, vv.w), aa);
            vv = Vg[2 * (Dv / 4)]; aa = pack2(a4.z, a4.z);
            ffma2(a01, pack2(vv.x, vv.y), aa);
            ffma2(a23, pack2(vv.z, vv.w), aa);
            vv = Vg[3 * (Dv / 4)]; aa = pack2(a4.w, a4.w);
            ffma2(a01, pack2(vv.x, vv.y), aa);
            ffma2(a23, pack2(vv.z, vv.w), aa);
            Vg += 4 * (Dv / 4);
        }
        const float2 e01 = unpack2(a01);
        const float2 e23 = unpack2(a23);
        float4 acc = make_float4(e01.x, e01.y, e23.x, e23.y);

        if (warp >= 4)
            *(float4*)&part[q][dof] = acc;
        __syncthreads();
        if (warp < 4) {
            const float4 pp = *(const float4*)&part[q][dof];
            acc.x += pp.x; acc.y += pp.y; acc.z += pp.z; acc.w += pp.w;
            *(float4*)(O + qbase + (size_t)q * Dv + dof) = acc;
        }
    }
}

extern "C" void kernel_launch(void* const* d_in, const int* in_sizes, int n_in,
                              void* d_out, int out_size)
{
    const float* Q  = (const float*)d_in[0];
    const float* K  = (const float*)d_in[1];
    const float* V  = (const float*)d_in[2];
    const float* LS = (const float*)d_in[3];
    float* O = (float*)d_out;

    const int BH = in_sizes[0] / (Lv * Dv);   // B*H = 32
    signed_attn_kernel<<<BH * NP, NT>>>(Q, K, V, LS, O);
}